// round 5
// baseline (speedup 1.0000x reference)
#include <cuda_runtime.h>

// FD_discretizer: fused, KY=2, float4-AoS shared-memory stencil.
// 1024x1024 grid, extended 1026x1026. Index arrays closed-form in (i,j).
// Identities: obm == ebm[interior]; interior ext == raw uvp.
// smem layout (grouped by tap pattern):
//   A = {eu, ev, ep, eou}   read at 9 taps
//   X = {U, Uo, a11, pxx}   read at l,c,r
//   Y = {V, Vo, a22, pex}   read at d,c,u
//   Z = {eov, pxy, pey, rJ} read at c,l,r,d,u

#define NXg 1024
#define NYg 1024
#define EX  1026
#define EY  1026
#define NN  (NXg*NYg)

#define PRESS_E (513*EX + 513)

#define TXg 32
#define TYg 8
#define KY  2
#define NTHR (TXg*TYg)           // 256
#define OUT_H (TYg*KY)           // 16
#define EXT_W (TXg + 2)          // 34
#define EXT_H (OUT_H + 2)        // 18
#define TILE  (EXT_W * EXT_H)    // 612

__device__ __forceinline__ int clampi(int x, int lo, int hi) {
    return x < lo ? lo : (x > hi ? hi : x);
}
__device__ __forceinline__ int eidx(int je, int ie) {
    return clampi(je - 1, 0, NYg - 1) * NXg + clampi(ie - 1, 0, NXg - 1);
}

struct F3 { float x, y, z; };

__device__ __forceinline__ void dummy_uv(const float* __restrict__ uvp,
                                         const float* __restrict__ ny,
                                         int m, float& du, float& dv) {
    int io = m % NXg;
    int jo = m / NXg;
    bool bc = (io == 0) || (io != NXg - 1 && (jo == 0 || jo == NYg - 1));
    if (bc) { du = ny[3*m]; dv = ny[3*m+1]; }
    else    { du = uvp[3*m]; dv = uvp[3*m+1]; }
}
__device__ __forceinline__ float dummy_p(const float* __restrict__ uvp, int m) {
    int io = m % NXg;
    return (io == NXg - 1) ? 0.0f : uvp[3*m+2];
}

__device__ __forceinline__ F3 ext_val(const float* __restrict__ uvp,
                                      const float* __restrict__ ny,
                                      int je, int ie) {
    F3 r;
    bool jin = (je >= 1) & (je <= EY - 2);
    if (ie == 0 && jin) {               // left ghost: INFLOW -> pmask
        int m1 = eidx(je, 1), m2 = eidx(je, 2);
        float du, dv; dummy_uv(uvp, ny, m1, du, dv);
        r.x = 2.0f*du - uvp[3*m2];
        r.y = 2.0f*dv - uvp[3*m2+1];
        r.z = uvp[3*m2+2];
    } else if (ie == EX - 1 && jin) {   // right ghost: OUTFLOW -> uvmask
        int m1 = eidx(je, EX - 2), m2 = eidx(je, EX - 3);
        float dp = dummy_p(uvp, m1);
        r.x = uvp[3*m2];
        r.y = uvp[3*m2+1];
        r.z = 2.0f*dp - uvp[3*m2+2];
    } else if (je == 0 && ie >= 1 && ie <= EX - 2) {   // bottom ghost: WALL
        int m1 = eidx(1, ie), m2 = eidx(2, ie);
        float du, dv; dummy_uv(uvp, ny, m1, du, dv);
        r.x = 2.0f*du - uvp[3*m2];
        r.y = 2.0f*dv - uvp[3*m2+1];
        r.z = uvp[3*m2+2];
    } else if (je == EY - 1 && ie >= 1 && ie <= EX - 2) {  // top ghost: WALL
        int m1 = eidx(EY - 2, ie), m2 = eidx(EY - 3, ie);
        float du, dv; dummy_uv(uvp, ny, m1, du, dv);
        r.x = 2.0f*du - uvp[3*m2];
        r.y = 2.0f*dv - uvp[3*m2+1];
        r.z = uvp[3*m2+2];
    } else {
        int m = eidx(je, ie);
        r.x = uvp[3*m]; r.y = uvp[3*m+1]; r.z = uvp[3*m+2];
    }
    return r;
}

__global__ void __launch_bounds__(NTHR, 5)
fused_kernel(const float* __restrict__ ouv,
             const float* __restrict__ ouv_old,
             const float* __restrict__ ny,
             const float* __restrict__ ebm,
             const float* __restrict__ dtg,
             const float* __restrict__ theta,
             const float* __restrict__ relp,
             float* __restrict__ out) {
    __shared__ float4 sA[TILE];   // {eu, ev, ep, eou}
    __shared__ float4 sX[TILE];   // {U, Uo, a11, pxx}
    __shared__ float4 sY[TILE];   // {V, Vo, a22, pex}
    __shared__ float4 sZ[TILE];   // {eov, pxy, pey, rJ}

    const int bx = blockIdx.x, by = blockIdx.y;
    const int lx = threadIdx.x, ly = threadIdx.y;
    const int tid = ly * TXg + lx;

    // ---- cooperative fill of extended tile ----
    for (int s = tid; s < TILE; s += NTHR) {
        int ly2 = s / EXT_W;
        int lx2 = s - ly2 * EXT_W;
        int ie = bx * TXg + lx2;
        int je = by * OUT_H + ly2;

        F3 en = ext_val(ouv,     ny, je, ie);
        F3 eo = ext_val(ouv_old, ny, je, ie);
        int e = je * EX + ie;
        if (e == PRESS_E) en.z = 0.0f;

        float dxx = ebm[5*e + 0];
        float dxy = ebm[5*e + 1];
        float dex = ebm[5*e + 2];
        float dey = ebm[5*e + 3];
        float Jm  = ebm[5*e + 4];
        float rJ  = __fdividef(1.0f, Jm);
        float pq  = en.z * rJ;

        sA[s] = make_float4(en.x, en.y, en.z, eo.x);
        sX[s] = make_float4((en.x*dxx + en.y*dxy) * rJ,
                            (eo.x*dxx + eo.y*dxy) * rJ,
                            (dxx*dxx + dxy*dxy) * rJ,
                            pq * dxx);
        sY[s] = make_float4((en.x*dex + en.y*dey) * rJ,
                            (eo.x*dex + eo.y*dey) * rJ,
                            (dex*dex + dey*dey) * rJ,
                            pq * dex);
        sZ[s] = make_float4(eo.y, pq * dxy, pq * dey, rJ);
    }
    __syncthreads();

    // ---- per-thread KY outputs ----
    const float rdt   = __fdividef(1.0f, __ldg(dtg));
    const float uc    = __ldg(theta + 0);
    const float cc    = __ldg(theta + 1);
    const float convc = __ldg(theta + 2);
    const float pc    = __ldg(theta + 3);
    const float dc    = __ldg(theta + 4);
    const float relax = __ldg(relp);

    const int io = bx * TXg + lx;
    const int jo0 = by * OUT_H + KY * ly;

    #pragma unroll
    for (int ky = 0; ky < KY; ky++) {
        const int c = (KY * ly + ky + 1) * EXT_W + (lx + 1);
        const int l = c - 1,      r = c + 1;
        const int d = c - EXT_W,  u = c + EXT_W;

        float4 Xl = sX[l], Xc = sX[c], Xr = sX[r];
        float4 Yd = sY[d], Yc = sY[c], Yu = sY[u];
        float4 Zl = sZ[l], Zc = sZ[c], Zr = sZ[r], Zd = sZ[d], Zu = sZ[u];
        float4 Al = sA[l], Ac = sA[c], Ar = sA[r], Ad = sA[d], Au = sA[u];

        // continuity
        float loss = 0.5f * ((Xr.x - Xl.x) + (Yu.x - Yd.x)) * cc;

        // convection (new): eu=A.x, ev=A.y, U=X.x, V=Y.x
        float cnu = 0.25f * ((Ac.x + Ar.x) * (Xc.x + Xr.x) - (Al.x + Ac.x) * (Xl.x + Xc.x))
                  + 0.25f * ((Ac.x + Au.x) * (Yc.x + Yu.x) - (Ad.x + Ac.x) * (Yd.x + Yc.x));
        float cnv = 0.25f * ((Ac.y + Ar.y) * (Xc.x + Xr.x) - (Al.y + Ac.y) * (Xl.x + Xc.x))
                  + 0.25f * ((Ac.y + Au.y) * (Yc.x + Yu.x) - (Ad.y + Ac.y) * (Yd.x + Yc.x));

        // convection (old): eou=A.w, eov=Z.x, Uo=X.y, Vo=Y.y
        float cou = 0.25f * ((Ac.w + Ar.w) * (Xc.y + Xr.y) - (Al.w + Ac.w) * (Xl.y + Xc.y))
                  + 0.25f * ((Ac.w + Au.w) * (Yc.y + Yu.y) - (Ad.w + Ac.w) * (Yd.y + Yc.y));
        float cov = 0.25f * ((Zc.x + Zr.x) * (Xc.y + Xr.y) - (Zl.x + Zc.x) * (Xl.y + Xc.y))
                  + 0.25f * ((Zc.x + Zu.x) * (Yc.y + Yu.y) - (Zd.x + Zc.x) * (Yd.y + Yc.y));

        float convu = relax * cou + (1.0f - relax) * cnu;
        float convv = relax * cov + (1.0f - relax) * cnv;

        // diffusion: a11=X.z, a22=Y.z
        float difu = 0.5f * ((Xc.z + Xr.z) * (Ar.x - Ac.x) - (Xl.z + Xc.z) * (Ac.x - Al.x))
                   + 0.5f * ((Yc.z + Yu.z) * (Au.x - Ac.x) - (Yd.z + Yc.z) * (Ac.x - Ad.x));
        float difv = 0.5f * ((Xc.z + Xr.z) * (Ar.y - Ac.y) - (Xl.z + Xc.z) * (Ac.y - Al.y))
                   + 0.5f * ((Yc.z + Yu.z) * (Au.y - Ac.y) - (Yd.z + Yc.z) * (Ac.y - Ad.y));

        // pressure gradient: pxx=X.w, pex=Y.w, pxy=Z.y, pey=Z.z
        float gPx = 0.5f * (Xr.w - Xl.w) + 0.5f * (Yu.w - Yd.w);
        float gPy = 0.5f * (Zu.z - Zd.z) + 0.5f * (Zr.y - Zl.y);

        // unsteady: rJ=Z.w (J_o == Jm at interior)
        float inv = Zc.w * rdt;
        float unu = (Ac.x - Ac.w) * inv;
        float unv = (Ac.y - Zc.x) * inv;

        float momu = uc * unu + convc * convu + pc * gPx - dc * difu;
        float momv = uc * unv + convc * convv + pc * gPy - dc * difv;

        // uvp_to_vis: (1-2-1)^2 / 16 binomial over eu,ev,ep (A.xyz)
        float4 Adl = sA[d-1], Adr = sA[d+1], Aul = sA[u-1], Aur = sA[u+1];
        const float sw = 1.0f / 16.0f;
        float visu = sw * (4.0f*Ac.x + 2.0f*(Al.x + Ar.x + Ad.x + Au.x)
                           + (Adl.x + Adr.x + Aul.x + Aur.x));
        float visv = sw * (4.0f*Ac.y + 2.0f*(Al.y + Ar.y + Ad.y + Au.y)
                           + (Adl.y + Adr.y + Aul.y + Aur.y));
        float visp = sw * (4.0f*Ac.z + 2.0f*(Al.z + Ar.z + Ad.z + Au.z)
                           + (Adl.z + Adr.z + Aul.z + Aur.z));

        const int o = (jo0 + ky) * NXg + io;
        out[o]          = loss;
        out[NN + o]     = momu;
        out[2*NN + o]   = momv;
        out[3*NN + 3*o]     = visu;
        out[3*NN + 3*o + 1] = visv;
        out[3*NN + 3*o + 2] = visp;
    }
}

extern "C" void kernel_launch(void* const* d_in, const int* in_sizes, int n_in,
                              void* d_out, int out_size) {
    const float* ouv     = (const float*)d_in[0];
    const float* ouv_old = (const float*)d_in[1];
    const float* ny      = (const float*)d_in[2];
    // d_in[3] (obm) unused: obm == ebm[interior]
    const float* ebm     = (const float*)d_in[4];
    const float* dtg     = (const float*)d_in[5];
    const float* theta   = (const float*)d_in[6];
    const float* relp    = (const float*)d_in[7];
    float* out = (float*)d_out;

    dim3 block(TXg, TYg);
    dim3 grid(NXg / TXg, NYg / OUT_H);
    fused_kernel<<<grid, block>>>(ouv, ouv_old, ny, ebm, dtg, theta, relp, out);
}

// round 6
// speedup vs baseline: 1.4039x; 1.4039x over previous
#include <cuda_runtime.h>

// FD_discretizer: fused, KY=2, float2-paired shared-memory stencil.
// Pairs grouped by tap pattern so no padding bytes are ever loaded:
//   {eu,ev} 9-tap, {ep,eou} 5-tap(+ep diag), {U,Uo} l/c/r, {V,Vo} d/c/u,
//   {a11,pxx} l/r, {a22,pex} d/u, {eov,rJ} center; pxy,pey scalar.
// Identities: obm == ebm[interior]; interior ext == raw uvp.

#define NXg 1024
#define NYg 1024
#define EX  1026
#define EY  1026
#define NN  (NXg*NYg)

#define PRESS_E (513*EX + 513)

#define TXg 32
#define TYg 8
#define KY  2
#define NTHR (TXg*TYg)           // 256
#define OUT_H (TYg*KY)           // 16
#define EXT_W (TXg + 2)          // 34
#define EXT_H (OUT_H + 2)        // 18
#define TILE  (EXT_W * EXT_H)    // 612

__device__ __forceinline__ int clampi(int x, int lo, int hi) {
    return x < lo ? lo : (x > hi ? hi : x);
}
__device__ __forceinline__ int eidx(int je, int ie) {
    return clampi(je - 1, 0, NYg - 1) * NXg + clampi(ie - 1, 0, NXg - 1);
}

struct F3 { float x, y, z; };

__device__ __forceinline__ void dummy_uv(const float* __restrict__ uvp,
                                         const float* __restrict__ ny,
                                         int m, float& du, float& dv) {
    int io = m % NXg;
    int jo = m / NXg;
    bool bc = (io == 0) || (io != NXg - 1 && (jo == 0 || jo == NYg - 1));
    if (bc) { du = ny[3*m]; dv = ny[3*m+1]; }
    else    { du = uvp[3*m]; dv = uvp[3*m+1]; }
}
__device__ __forceinline__ float dummy_p(const float* __restrict__ uvp, int m) {
    int io = m % NXg;
    return (io == NXg - 1) ? 0.0f : uvp[3*m+2];
}

__device__ __forceinline__ F3 ext_val(const float* __restrict__ uvp,
                                      const float* __restrict__ ny,
                                      int je, int ie) {
    F3 r;
    bool jin = (je >= 1) & (je <= EY - 2);
    if (ie == 0 && jin) {               // left ghost: INFLOW -> pmask
        int m1 = eidx(je, 1), m2 = eidx(je, 2);
        float du, dv; dummy_uv(uvp, ny, m1, du, dv);
        r.x = 2.0f*du - uvp[3*m2];
        r.y = 2.0f*dv - uvp[3*m2+1];
        r.z = uvp[3*m2+2];
    } else if (ie == EX - 1 && jin) {   // right ghost: OUTFLOW -> uvmask
        int m1 = eidx(je, EX - 2), m2 = eidx(je, EX - 3);
        float dp = dummy_p(uvp, m1);
        r.x = uvp[3*m2];
        r.y = uvp[3*m2+1];
        r.z = 2.0f*dp - uvp[3*m2+2];
    } else if (je == 0 && ie >= 1 && ie <= EX - 2) {   // bottom ghost: WALL
        int m1 = eidx(1, ie), m2 = eidx(2, ie);
        float du, dv; dummy_uv(uvp, ny, m1, du, dv);
        r.x = 2.0f*du - uvp[3*m2];
        r.y = 2.0f*dv - uvp[3*m2+1];
        r.z = uvp[3*m2+2];
    } else if (je == EY - 1 && ie >= 1 && ie <= EX - 2) {  // top ghost: WALL
        int m1 = eidx(EY - 2, ie), m2 = eidx(EY - 3, ie);
        float du, dv; dummy_uv(uvp, ny, m1, du, dv);
        r.x = 2.0f*du - uvp[3*m2];
        r.y = 2.0f*dv - uvp[3*m2+1];
        r.z = uvp[3*m2+2];
    } else {
        int m = eidx(je, ie);
        r.x = uvp[3*m]; r.y = uvp[3*m+1]; r.z = uvp[3*m+2];
    }
    return r;
}

__global__ void __launch_bounds__(NTHR, 5)
fused_kernel(const float* __restrict__ ouv,
             const float* __restrict__ ouv_old,
             const float* __restrict__ ny,
             const float* __restrict__ ebm,
             const float* __restrict__ dtg,
             const float* __restrict__ theta,
             const float* __restrict__ relp,
             float* __restrict__ out) {
    __shared__ float2 sUV[TILE];   // {eu, ev}
    __shared__ float2 sPO[TILE];   // {ep, eou}
    __shared__ float2 sU [TILE];   // {U,  Uo}
    __shared__ float2 sAX[TILE];   // {a11, pxx}
    __shared__ float2 sV [TILE];   // {V,  Vo}
    __shared__ float2 sAY[TILE];   // {a22, pex}
    __shared__ float2 sOR[TILE];   // {eov, rJ}
    __shared__ float  sXY[TILE];   // pxy
    __shared__ float  sEY[TILE];   // pey

    const int bx = blockIdx.x, by = blockIdx.y;
    const int lx = threadIdx.x, ly = threadIdx.y;
    const int tid = ly * TXg + lx;

    // ---- cooperative fill of extended tile ----
    for (int s = tid; s < TILE; s += NTHR) {
        int ly2 = s / EXT_W;
        int lx2 = s - ly2 * EXT_W;
        int ie = bx * TXg + lx2;
        int je = by * OUT_H + ly2;

        F3 en = ext_val(ouv,     ny, je, ie);
        F3 eo = ext_val(ouv_old, ny, je, ie);
        int e = je * EX + ie;
        if (e == PRESS_E) en.z = 0.0f;

        float dxx = ebm[5*e + 0];
        float dxy = ebm[5*e + 1];
        float dex = ebm[5*e + 2];
        float dey = ebm[5*e + 3];
        float Jm  = ebm[5*e + 4];
        float rJ  = __fdividef(1.0f, Jm);
        float pq  = en.z * rJ;

        sUV[s] = make_float2(en.x, en.y);
        sPO[s] = make_float2(en.z, eo.x);
        sU [s] = make_float2((en.x*dxx + en.y*dxy) * rJ,
                             (eo.x*dxx + eo.y*dxy) * rJ);
        sAX[s] = make_float2((dxx*dxx + dxy*dxy) * rJ, pq * dxx);
        sV [s] = make_float2((en.x*dex + en.y*dey) * rJ,
                             (eo.x*dex + eo.y*dey) * rJ);
        sAY[s] = make_float2((dex*dex + dey*dey) * rJ, pq * dex);
        sOR[s] = make_float2(eo.y, rJ);
        sXY[s] = pq * dxy;
        sEY[s] = pq * dey;
    }
    __syncthreads();

    // ---- per-thread KY outputs ----
    const float rdt   = __fdividef(1.0f, __ldg(dtg));
    const float uc    = __ldg(theta + 0);
    const float cc    = __ldg(theta + 1);
    const float convc = __ldg(theta + 2);
    const float pc    = __ldg(theta + 3);
    const float dc    = __ldg(theta + 4);
    const float relax = __ldg(relp);

    const int io = bx * TXg + lx;
    const int jo0 = by * OUT_H + KY * ly;

    #pragma unroll
    for (int ky = 0; ky < KY; ky++) {
        const int c = (KY * ly + ky + 1) * EXT_W + (lx + 1);
        const int l = c - 1,      r = c + 1;
        const int d = c - EXT_W,  u = c + EXT_W;

        float2 Ul = sU[l], Uc = sU[c], Ur = sU[r];        // .x=U, .y=Uo
        float2 Vd = sV[d], Vc = sV[c], Vu = sV[u];        // .x=V, .y=Vo

        float loss = 0.5f * ((Ur.x - Ul.x) + (Vu.x - Vd.x)) * cc;

        float2 uvL = sUV[l], uvC = sUV[c], uvR = sUV[r], uvD = sUV[d], uvU = sUV[u];
        float2 uvDL = sUV[d-1], uvDR = sUV[d+1], uvUL = sUV[u-1], uvUR = sUV[u+1];
        float2 poL = sPO[l], poC = sPO[c], poR = sPO[r], poD = sPO[d], poU = sPO[u];
        float epdl = sPO[d-1].x, epdr = sPO[d+1].x, epul = sPO[u-1].x, epur = sPO[u+1].x;

        // convection (new)
        float sxU = Uc.x + Ur.x, sxL = Ul.x + Uc.x;
        float syU = Vc.x + Vu.x, syD = Vd.x + Vc.x;
        float cnu = 0.25f * ((uvC.x + uvR.x) * sxU - (uvL.x + uvC.x) * sxL)
                  + 0.25f * ((uvC.x + uvU.x) * syU - (uvD.x + uvC.x) * syD);
        float cnv = 0.25f * ((uvC.y + uvR.y) * sxU - (uvL.y + uvC.y) * sxL)
                  + 0.25f * ((uvC.y + uvU.y) * syU - (uvD.y + uvC.y) * syD);

        // convection (old): eou = po.y, eov from sOR.x
        float2 orC = sOR[c];
        float eovl = sOR[l].x, eovr = sOR[r].x, eovd = sOR[d].x, eovu = sOR[u].x;
        float oxU = Uc.y + Ur.y, oxL = Ul.y + Uc.y;
        float oyU = Vc.y + Vu.y, oyD = Vd.y + Vc.y;
        float cou = 0.25f * ((poC.y + poR.y) * oxU - (poL.y + poC.y) * oxL)
                  + 0.25f * ((poC.y + poU.y) * oyU - (poD.y + poC.y) * oyD);
        float cov = 0.25f * ((orC.x + eovr) * oxU - (eovl + orC.x) * oxL)
                  + 0.25f * ((orC.x + eovu) * oyU - (eovd + orC.x) * oyD);

        float convu = relax * cou + (1.0f - relax) * cnu;
        float convv = relax * cov + (1.0f - relax) * cnv;

        // diffusion: a11 = sAX.x (l,c,r), a22 = sAY.x (d,c,u)
        float2 axL = sAX[l], axR = sAX[r];
        float2 ayD = sAY[d], ayU = sAY[u];
        float a11c = sAX[c].x, a22c = sAY[c].x;
        float wxr = a11c + axR.x, wxl = axL.x + a11c;
        float wyu = a22c + ayU.x, wyd = ayD.x + a22c;
        float difu = 0.5f * (wxr * (uvR.x - uvC.x) - wxl * (uvC.x - uvL.x))
                   + 0.5f * (wyu * (uvU.x - uvC.x) - wyd * (uvC.x - uvD.x));
        float difv = 0.5f * (wxr * (uvR.y - uvC.y) - wxl * (uvC.y - uvL.y))
                   + 0.5f * (wyu * (uvU.y - uvC.y) - wyd * (uvC.y - uvD.y));

        // pressure gradient: pxx = sAX.y, pex = sAY.y, pxy/pey scalar
        float gPx = 0.5f * (axR.y - axL.y) + 0.5f * (ayU.y - ayD.y);
        float gPy = 0.5f * (sEY[u] - sEY[d]) + 0.5f * (sXY[r] - sXY[l]);

        // unsteady: rJ = orC.y (J_o == Jm at interior)
        float inv = orC.y * rdt;
        float unu = (uvC.x - poC.y) * inv;
        float unv = (uvC.y - orC.x) * inv;

        float momu = uc * unu + convc * convu + pc * gPx - dc * difu;
        float momv = uc * unv + convc * convv + pc * gPy - dc * difv;

        // uvp_to_vis: (1-2-1)^2 / 16 binomial
        const float sw = 1.0f / 16.0f;
        float visu = sw * (4.0f*uvC.x + 2.0f*(uvL.x + uvR.x + uvD.x + uvU.x)
                           + (uvDL.x + uvDR.x + uvUL.x + uvUR.x));
        float visv = sw * (4.0f*uvC.y + 2.0f*(uvL.y + uvR.y + uvD.y + uvU.y)
                           + (uvDL.y + uvDR.y + uvUL.y + uvUR.y));
        float visp = sw * (4.0f*poC.x + 2.0f*(poL.x + poR.x + poD.x + poU.x)
                           + (epdl + epdr + epul + epur));

        const int o = (jo0 + ky) * NXg + io;
        out[o]          = loss;
        out[NN + o]     = momu;
        out[2*NN + o]   = momv;
        out[3*NN + 3*o]     = visu;
        out[3*NN + 3*o + 1] = visv;
        out[3*NN + 3*o + 2] = visp;
    }
}

extern "C" void kernel_launch(void* const* d_in, const int* in_sizes, int n_in,
                              void* d_out, int out_size) {
    const float* ouv     = (const float*)d_in[0];
    const float* ouv_old = (const float*)d_in[1];
    const float* ny      = (const float*)d_in[2];
    // d_in[3] (obm) unused: obm == ebm[interior]
    const float* ebm     = (const float*)d_in[4];
    const float* dtg     = (const float*)d_in[5];
    const float* theta   = (const float*)d_in[6];
    const float* relp    = (const float*)d_in[7];
    float* out = (float*)d_out;

    dim3 block(TXg, TYg);
    dim3 grid(NXg / TXg, NYg / OUT_H);
    fused_kernel<<<grid, block>>>(ouv, ouv_old, ny, ebm, dtg, theta, relp, out);
}

// round 7
// speedup vs baseline: 1.4849x; 1.0577x over previous
#include <cuda_runtime.h>

// FD_discretizer: fused, KY=2, scalar-smem stencil (R4 shape), 6 blocks/SM.
// 15 smem arrays (rJ dropped; consumer reads center Jm from ebm via L2).
// Identities: obm == ebm[interior]; interior ext == raw uvp.

#define NXg 1024
#define NYg 1024
#define EX  1026
#define EY  1026
#define NN  (NXg*NYg)

#define PRESS_E (513*EX + 513)

#define TXg 32
#define TYg 8
#define KY  2
#define NTHR (TXg*TYg)           // 256
#define OUT_H (TYg*KY)           // 16
#define EXT_W (TXg + 2)          // 34
#define EXT_H (OUT_H + 2)        // 18
#define TILE  (EXT_W * EXT_H)    // 612

__device__ __forceinline__ int clampi(int x, int lo, int hi) {
    return x < lo ? lo : (x > hi ? hi : x);
}
__device__ __forceinline__ int eidx(int je, int ie) {
    return clampi(je - 1, 0, NYg - 1) * NXg + clampi(ie - 1, 0, NXg - 1);
}

struct F3 { float x, y, z; };

__device__ __forceinline__ void dummy_uv(const float* __restrict__ uvp,
                                         const float* __restrict__ ny,
                                         int m, float& du, float& dv) {
    int io = m % NXg;
    int jo = m / NXg;
    bool bc = (io == 0) || (io != NXg - 1 && (jo == 0 || jo == NYg - 1));
    if (bc) { du = ny[3*m]; dv = ny[3*m+1]; }
    else    { du = uvp[3*m]; dv = uvp[3*m+1]; }
}
__device__ __forceinline__ float dummy_p(const float* __restrict__ uvp, int m) {
    int io = m % NXg;
    return (io == NXg - 1) ? 0.0f : uvp[3*m+2];
}

// pmask-style ghost (INFLOW/WALL): uv mirrored through dummy, p copied
__device__ __forceinline__ F3 ghost_pmask(const float* __restrict__ f,
                                          const float* __restrict__ ny,
                                          int m1, int m2) {
    F3 r;
    float du, dv; dummy_uv(f, ny, m1, du, dv);
    r.x = 2.0f*du - f[3*m2];
    r.y = 2.0f*dv - f[3*m2+1];
    r.z = f[3*m2+2];
    return r;
}
// uvmask-style ghost (OUTFLOW): uv copied, p mirrored through dummy
__device__ __forceinline__ F3 ghost_uvmask(const float* __restrict__ f,
                                           int m1, int m2) {
    F3 r;
    float dp = dummy_p(f, m1);
    r.x = f[3*m2];
    r.y = f[3*m2+1];
    r.z = 2.0f*dp - f[3*m2+2];
    return r;
}
__device__ __forceinline__ F3 load3(const float* __restrict__ f, int m) {
    F3 r; r.x = f[3*m]; r.y = f[3*m+1]; r.z = f[3*m+2]; return r;
}

// Evaluate BC-enforced extension for both fields with one branch resolution.
__device__ __forceinline__ void ext_pair(const float* __restrict__ uvp,
                                         const float* __restrict__ old_,
                                         const float* __restrict__ ny,
                                         int je, int ie, F3& en, F3& eo) {
    bool jin = (je >= 1) & (je <= EY - 2);
    if (ie == 0 && jin) {                       // left: INFLOW -> pmask
        int m1 = eidx(je, 1), m2 = eidx(je, 2);
        en = ghost_pmask(uvp, ny, m1, m2);
        eo = ghost_pmask(old_, ny, m1, m2);
    } else if (ie == EX - 1 && jin) {           // right: OUTFLOW -> uvmask
        int m1 = eidx(je, EX - 2), m2 = eidx(je, EX - 3);
        en = ghost_uvmask(uvp, m1, m2);
        eo = ghost_uvmask(old_, m1, m2);
    } else if (je == 0 && ie >= 1 && ie <= EX - 2) {   // bottom: WALL
        int m1 = eidx(1, ie), m2 = eidx(2, ie);
        en = ghost_pmask(uvp, ny, m1, m2);
        eo = ghost_pmask(old_, ny, m1, m2);
    } else if (je == EY - 1 && ie >= 1 && ie <= EX - 2) {  // top: WALL
        int m1 = eidx(EY - 2, ie), m2 = eidx(EY - 3, ie);
        en = ghost_pmask(uvp, ny, m1, m2);
        eo = ghost_pmask(old_, ny, m1, m2);
    } else {
        int m = eidx(je, ie);
        en = load3(uvp, m);
        eo = load3(old_, m);
    }
}

__global__ void __launch_bounds__(NTHR, 6)
fused_kernel(const float* __restrict__ ouv,
             const float* __restrict__ ouv_old,
             const float* __restrict__ ny,
             const float* __restrict__ ebm,
             const float* __restrict__ dtg,
             const float* __restrict__ theta,
             const float* __restrict__ relp,
             float* __restrict__ out) {
    __shared__ float s_eu [TILE];
    __shared__ float s_ev [TILE];
    __shared__ float s_ep [TILE];
    __shared__ float s_eou[TILE];
    __shared__ float s_eov[TILE];
    __shared__ float s_U  [TILE];
    __shared__ float s_V  [TILE];
    __shared__ float s_Uo [TILE];
    __shared__ float s_Vo [TILE];
    __shared__ float s_a11[TILE];
    __shared__ float s_a22[TILE];
    __shared__ float s_pxx[TILE];
    __shared__ float s_pxy[TILE];
    __shared__ float s_pex[TILE];
    __shared__ float s_pey[TILE];

    const int bx = blockIdx.x, by = blockIdx.y;
    const int lx = threadIdx.x, ly = threadIdx.y;
    const int tid = ly * TXg + lx;

    // ---- cooperative fill of extended tile ----
    for (int s = tid; s < TILE; s += NTHR) {
        int ly2 = s / EXT_W;
        int lx2 = s - ly2 * EXT_W;
        int ie = bx * TXg + lx2;
        int je = by * OUT_H + ly2;

        F3 en, eo;
        ext_pair(ouv, ouv_old, ny, je, ie, en, eo);
        int e = je * EX + ie;
        if (e == PRESS_E) en.z = 0.0f;

        float dxx = ebm[5*e + 0];
        float dxy = ebm[5*e + 1];
        float dex = ebm[5*e + 2];
        float dey = ebm[5*e + 3];
        float Jm  = ebm[5*e + 4];
        float rJ  = __fdividef(1.0f, Jm);
        float pq  = en.z * rJ;

        s_eu [s] = en.x;  s_ev [s] = en.y;  s_ep [s] = en.z;
        s_eou[s] = eo.x;  s_eov[s] = eo.y;
        s_U  [s] = (en.x*dxx + en.y*dxy) * rJ;
        s_V  [s] = (en.x*dex + en.y*dey) * rJ;
        s_Uo [s] = (eo.x*dxx + eo.y*dxy) * rJ;
        s_Vo [s] = (eo.x*dex + eo.y*dey) * rJ;
        s_a11[s] = (dxx*dxx + dxy*dxy) * rJ;
        s_a22[s] = (dex*dex + dey*dey) * rJ;
        s_pxx[s] = pq * dxx;
        s_pxy[s] = pq * dxy;
        s_pex[s] = pq * dex;
        s_pey[s] = pq * dey;
    }
    __syncthreads();

    // ---- per-thread KY outputs, direct smem reads ----
    const float dt    = __ldg(dtg);
    const float uc    = __ldg(theta + 0);
    const float cc    = __ldg(theta + 1);
    const float convc = __ldg(theta + 2);
    const float pc    = __ldg(theta + 3);
    const float dc    = __ldg(theta + 4);
    const float relax = __ldg(relp);

    const int io = bx * TXg + lx;
    const int jo0 = by * OUT_H + KY * ly;

    #pragma unroll
    for (int ky = 0; ky < KY; ky++) {
        const int c = (KY * ly + ky + 1) * EXT_W + (lx + 1);
        const int l = c - 1,      r = c + 1;
        const int d = c - EXT_W,  u = c + EXT_W;

        float Uc = s_U[c], Ul = s_U[l], Ur = s_U[r];
        float Vc = s_V[c], Vd = s_V[d], Vu = s_V[u];
        float loss = 0.5f * ((Ur - Ul) + (Vu - Vd)) * cc;

        float euc = s_eu[c], eul = s_eu[l], eur = s_eu[r], eud = s_eu[d], euu = s_eu[u];
        float evc = s_ev[c], evl = s_ev[l], evr = s_ev[r], evd = s_ev[d], evu = s_ev[u];
        float epc = s_ep[c], epl = s_ep[l], epr = s_ep[r], epd = s_ep[d], epu = s_ep[u];
        float eudl = s_eu[d-1], eudr = s_eu[d+1], euul = s_eu[u-1], euur = s_eu[u+1];
        float evdl = s_ev[d-1], evdr = s_ev[d+1], evul = s_ev[u-1], evur = s_ev[u+1];
        float epdl = s_ep[d-1], epdr = s_ep[d+1], epul = s_ep[u-1], epur = s_ep[u+1];

        // convection (new)
        float cnu = 0.25f * ((euc + eur) * (Uc + Ur) - (eul + euc) * (Ul + Uc))
                  + 0.25f * ((euc + euu) * (Vc + Vu) - (eud + euc) * (Vd + Vc));
        float cnv = 0.25f * ((evc + evr) * (Uc + Ur) - (evl + evc) * (Ul + Uc))
                  + 0.25f * ((evc + evu) * (Vc + Vu) - (evd + evc) * (Vd + Vc));

        // convection (old)
        float Uoc = s_Uo[c], Uol = s_Uo[l], Uor = s_Uo[r];
        float Voc = s_Vo[c], Vod = s_Vo[d], Vou = s_Vo[u];
        float ouc = s_eou[c], oul = s_eou[l], our = s_eou[r], oud = s_eou[d], ouu = s_eou[u];
        float ovc = s_eov[c], ovl = s_eov[l], ovr = s_eov[r], ovd = s_eov[d], ovu = s_eov[u];

        float cou = 0.25f * ((ouc + our) * (Uoc + Uor) - (oul + ouc) * (Uol + Uoc))
                  + 0.25f * ((ouc + ouu) * (Voc + Vou) - (oud + ouc) * (Vod + Voc));
        float cov = 0.25f * ((ovc + ovr) * (Uoc + Uor) - (ovl + ovc) * (Uol + Uoc))
                  + 0.25f * ((ovc + ovu) * (Voc + Vou) - (ovd + ovc) * (Vod + Voc));

        float convu = relax * cou + (1.0f - relax) * cnu;
        float convv = relax * cov + (1.0f - relax) * cnv;

        // diffusion (new)
        float a11c = s_a11[c], a11l = s_a11[l], a11r = s_a11[r];
        float a22c = s_a22[c], a22d = s_a22[d], a22u = s_a22[u];
        float difu = 0.5f * ((a11c + a11r) * (eur - euc) - (a11l + a11c) * (euc - eul))
                   + 0.5f * ((a22c + a22u) * (euu - euc) - (a22d + a22c) * (euc - eud));
        float difv = 0.5f * ((a11c + a11r) * (evr - evc) - (a11l + a11c) * (evc - evl))
                   + 0.5f * ((a22c + a22u) * (evu - evc) - (a22d + a22c) * (evc - evd));

        // pressure gradient
        float gPx = 0.5f * (s_pxx[r] - s_pxx[l]) + 0.5f * (s_pex[u] - s_pex[d]);
        float gPy = 0.5f * (s_pey[u] - s_pey[d]) + 0.5f * (s_pxy[r] - s_pxy[l]);

        // unsteady: J_o == Jm at interior ext node; read from ebm (L2-hot)
        const int jo = jo0 + ky;
        const int ec = (jo + 1) * EX + (io + 1);
        float Jm = __ldg(ebm + 5*ec + 4);
        float inv = __fdividef(1.0f, dt * Jm);
        float unu = (euc - ouc) * inv;
        float unv = (evc - ovc) * inv;

        float momu = uc * unu + convc * convu + pc * gPx - dc * difu;
        float momv = uc * unv + convc * convv + pc * gPy - dc * difv;

        // uvp_to_vis: (1-2-1)^2 / 16 binomial
        const float sw = 1.0f / 16.0f;
        float visu = sw * (4.0f*euc + 2.0f*(eul + eur + eud + euu) + (eudl + eudr + euul + euur));
        float visv = sw * (4.0f*evc + 2.0f*(evl + evr + evd + evu) + (evdl + evdr + evul + evur));
        float visp = sw * (4.0f*epc + 2.0f*(epl + epr + epd + epu) + (epdl + epdr + epul + epur));

        const int o = jo * NXg + io;
        out[o]          = loss;
        out[NN + o]     = momu;
        out[2*NN + o]   = momv;
        out[3*NN + 3*o]     = visu;
        out[3*NN + 3*o + 1] = visv;
        out[3*NN + 3*o + 2] = visp;
    }
}

extern "C" void kernel_launch(void* const* d_in, const int* in_sizes, int n_in,
                              void* d_out, int out_size) {
    const float* ouv     = (const float*)d_in[0];
    const float* ouv_old = (const float*)d_in[1];
    const float* ny      = (const float*)d_in[2];
    // d_in[3] (obm) unused: obm == ebm[interior]
    const float* ebm     = (const float*)d_in[4];
    const float* dtg     = (const float*)d_in[5];
    const float* theta   = (const float*)d_in[6];
    const float* relp    = (const float*)d_in[7];
    float* out = (float*)d_out;

    dim3 block(TXg, TYg);
    dim3 grid(NXg / TXg, NYg / OUT_H);
    fused_kernel<<<grid, block>>>(ouv, ouv_old, ny, ebm, dtg, theta, relp, out);
}